// round 11
// baseline (speedup 1.0000x reference)
#include <cuda_runtime.h>
#include <cstdint>

#define N_NODES 8192
#define C 256
#define NWORDS 256   // 8192 bits / 32 per row
#define MAXDEG 128
#define ROWS_PER_BLK 8

// Scratch (device globals — no allocation allowed)
__device__ unsigned g_bitmap[N_NODES * NWORDS];   // 8 MiB adjacency bitmap (self-cleaning)
__device__ float    g_xs[N_NODES * C];            // dis[j] * x[j]
__device__ float    g_dis[N_NODES];
__device__ float    g_pre[N_NODES * C];           // norm @ x
__device__ int      g_adj[N_NODES * MAXDEG];      // 4 MiB neighbor lists
__device__ int      g_cnt[N_NODES];

// packed fp32x2 add/mul (Blackwell baseline PTX, sm_100+)
#define ADDX2(acc, v) asm("add.rn.f32x2 %0, %0, %1;" : "+l"(acc) : "l"(v))
#define MULX2(acc, v) asm("mul.rn.f32x2 %0, %0, %1;" : "+l"(acc) : "l"(v))
__device__ __forceinline__ unsigned long long d2l(double d) {
    return __double_as_longlong(d);
}

// ---------------------------------------------------------------- K2: edges
__global__ void k_set_edges(const int* __restrict__ ei, int E) {
    int e = blockIdx.x * blockDim.x + threadIdx.x;
    if (e < E) {
        int r = ei[e]     & (N_NODES - 1);
        int c = ei[E + e] & (N_NODES - 1);
        atomicOr(&g_bitmap[r * NWORDS + (c >> 5)], 1u << (c & 31));
    }
}

// ----- K3: prep = degree + decode + prescale + bitmap self-clear (warp/row)
__global__ __launch_bounds__(256) void k_prep(const float* __restrict__ x) {
    int warp = threadIdx.x >> 5;
    int lane = threadIdx.x & 31;
    int row  = blockIdx.x * ROWS_PER_BLK + warp;
    unsigned* bm = &g_bitmap[row * NWORDS];
    unsigned w[8];
    *(uint4*)&w[0] = *(const uint4*)&bm[lane * 8];
    *(uint4*)&w[4] = *(const uint4*)&bm[lane * 8 + 4];
    uint4 z = make_uint4(0u, 0u, 0u, 0u);
    *(uint4*)&bm[lane * 8]     = z;
    *(uint4*)&bm[lane * 8 + 4] = z;

    int cnt = 0;
    #pragma unroll
    for (int q = 0; q < 8; q++) cnt += __popc(w[q]);
    int off = cnt;
    #pragma unroll
    for (int d = 1; d < 32; d <<= 1) {
        int v = __shfl_up_sync(0xFFFFFFFFu, off, d);
        if (lane >= d) off += v;
    }
    int total = __shfl_sync(0xFFFFFFFFu, off, 31);
    off -= cnt;
    int tclamp = total > MAXDEG ? MAXDEG : total;
    if (lane == 0) g_cnt[row] = tclamp;
    int p = off;
    int* adj = &g_adj[row * MAXDEG];
    #pragma unroll
    for (int q = 0; q < 8; q++) {
        unsigned word = w[q];
        while (word) {
            int b = __ffs(word) - 1;
            word &= word - 1;
            if (p < MAXDEG) adj[p] = ((lane * 8 + q) << 5) + b;
            p++;
        }
    }
    float dis = rsqrtf((float)(total + 1));
    if (lane == 0) g_dis[row] = dis;
    int ch = lane * 8;
    float4 v0 = *(const float4*)(x + row * C + ch);
    float4 v1 = *(const float4*)(x + row * C + ch + 4);
    v0.x *= dis; v0.y *= dis; v0.z *= dis; v0.w *= dis;
    v1.x *= dis; v1.y *= dis; v1.z *= dis; v1.w *= dis;
    *(float4*)(g_xs + row * C + ch)     = v0;
    *(float4*)(g_xs + row * C + ch + 4) = v1;
}

// --------------------------------------------------------------- K4: SpMM
__global__ __launch_bounds__(256) void k_spmm() {
    int warp = threadIdx.x >> 5;
    int lane = threadIdx.x & 31;
    int row  = blockIdx.x * 4 + (warp >> 1);
    int ch   = (warp & 1) * 128 + lane * 4;

    int cnt = g_cnt[row];
    const int* adj = &g_adj[row * MAXDEG];
    const float* xs = g_xs;

    double2 e = *(const double2*)(xs + row * C + ch);   // eye term (prescaled)
    unsigned long long acc0 = d2l(e.x);
    unsigned long long acc1 = d2l(e.y);

    int k = 0;
    for (; k + 8 <= cnt; k += 8) {
        int4 ja = *(const int4*)&adj[k];
        int4 jb = *(const int4*)&adj[k + 4];
        double2 v0 = *(const double2*)(xs + ja.x * C + ch);
        double2 v1 = *(const double2*)(xs + ja.y * C + ch);
        double2 v2 = *(const double2*)(xs + ja.z * C + ch);
        double2 v3 = *(const double2*)(xs + ja.w * C + ch);
        double2 v4 = *(const double2*)(xs + jb.x * C + ch);
        double2 v5 = *(const double2*)(xs + jb.y * C + ch);
        double2 v6 = *(const double2*)(xs + jb.z * C + ch);
        double2 v7 = *(const double2*)(xs + jb.w * C + ch);
        ADDX2(acc0, d2l(v0.x)); ADDX2(acc1, d2l(v0.y));
        ADDX2(acc0, d2l(v1.x)); ADDX2(acc1, d2l(v1.y));
        ADDX2(acc0, d2l(v2.x)); ADDX2(acc1, d2l(v2.y));
        ADDX2(acc0, d2l(v3.x)); ADDX2(acc1, d2l(v3.y));
        ADDX2(acc0, d2l(v4.x)); ADDX2(acc1, d2l(v4.y));
        ADDX2(acc0, d2l(v5.x)); ADDX2(acc1, d2l(v5.y));
        ADDX2(acc0, d2l(v6.x)); ADDX2(acc1, d2l(v6.y));
        ADDX2(acc0, d2l(v7.x)); ADDX2(acc1, d2l(v7.y));
    }
    for (; k + 4 <= cnt; k += 4) {
        int4 ja = *(const int4*)&adj[k];
        double2 v0 = *(const double2*)(xs + ja.x * C + ch);
        double2 v1 = *(const double2*)(xs + ja.y * C + ch);
        double2 v2 = *(const double2*)(xs + ja.z * C + ch);
        double2 v3 = *(const double2*)(xs + ja.w * C + ch);
        ADDX2(acc0, d2l(v0.x)); ADDX2(acc1, d2l(v0.y));
        ADDX2(acc0, d2l(v1.x)); ADDX2(acc1, d2l(v1.y));
        ADDX2(acc0, d2l(v2.x)); ADDX2(acc1, d2l(v2.y));
        ADDX2(acc0, d2l(v3.x)); ADDX2(acc1, d2l(v3.y));
    }
    for (; k < cnt; k++) {
        int j = adj[k];
        double2 v = *(const double2*)(xs + j * C + ch);
        ADDX2(acc0, d2l(v.x)); ADDX2(acc1, d2l(v.y));
    }

    float disI = g_dis[row];
    unsigned long long dp;
    asm("mov.b64 %0, {%1, %1};" : "=l"(dp) : "r"(__float_as_uint(disI)));
    MULX2(acc0, dp);
    MULX2(acc1, dp);
    double2 o;
    o.x = __longlong_as_double(acc0);
    o.y = __longlong_as_double(acc1);
    *(double2*)(g_pre + row * C + ch) = o;
}

// ------------------------------------------- K5: tf32 mma.sync GEMM
// out[8192,256] = pre @ W^T + b1 + b2.
// CTA tile 128x128, 512 threads / 16 warps (4x4), warp tile 32x32,
// K chunk 16, double-buffered smem.
#define GT_M 128
#define GT_N 128
#define KSTEP 16
#define NKC (C / KSTEP)   // 16
#define LDP 20            // padded smem row stride (floats); conflict-free

__device__ __forceinline__ uint32_t f2tf32(float f) {
    uint32_t r;
    asm("cvt.rna.tf32.f32 %0, %1;" : "=r"(r) : "f"(f));
    return r;
}
__device__ __forceinline__ uint4 cvt4(float4 v) {
    uint4 r;
    r.x = f2tf32(v.x); r.y = f2tf32(v.y); r.z = f2tf32(v.z); r.w = f2tf32(v.w);
    return r;
}
__device__ __forceinline__ void mma_tf32(float* c, const uint32_t* a, const uint32_t* b) {
    asm volatile(
        "mma.sync.aligned.m16n8k8.row.col.f32.tf32.tf32.f32 "
        "{%0,%1,%2,%3}, {%4,%5,%6,%7}, {%8,%9}, {%0,%1,%2,%3};"
        : "+f"(c[0]), "+f"(c[1]), "+f"(c[2]), "+f"(c[3])
        : "r"(a[0]), "r"(a[1]), "r"(a[2]), "r"(a[3]), "r"(b[0]), "r"(b[1]));
}

__global__ __launch_bounds__(512) void k_gemm_mma(
    const float* __restrict__ Wm,
    const float* __restrict__ b1,
    const float* __restrict__ b2,
    float* __restrict__ out)
{
    __shared__ uint32_t As[2][GT_M * LDP];
    __shared__ uint32_t Bs[2][GT_N * LDP];
    __shared__ float sbias[GT_N];

    int tid  = threadIdx.x;
    int wid  = tid >> 5;
    int lane = tid & 31;
    int wm   = wid >> 2;          // 0..3
    int wn   = wid & 3;           // 0..3
    int row0 = blockIdx.x * GT_M;
    int col0 = blockIdx.y * GT_N;

    if (tid < GT_N) sbias[tid] = b1[col0 + tid] + b2[col0 + tid];

    // gmem: one float4 per thread per tile per chunk
    int grow = tid >> 2;          // 0..127
    int gq   = tid & 3;           // 0..3
    const float* agm = g_pre + (size_t)(row0 + grow) * C + gq * 4;
    const float* bgm = Wm    + (size_t)(col0 + grow) * C + gq * 4;
    uint32_t sw = grow * LDP + gq * 4;

    float4 pa = *(const float4*)(agm);
    float4 pb = *(const float4*)(bgm);
    *(uint4*)&As[0][sw] = cvt4(pa);
    *(uint4*)&Bs[0][sw] = cvt4(pb);
    __syncthreads();

    float acc[2][4][4] = {};
    int l4 = lane >> 2;           // 0..7
    int lk = lane & 3;            // 0..3

    for (int kc = 0; kc < NKC; kc++) {
        int st = kc & 1;
        if (kc < NKC - 1) {
            int ko = (kc + 1) * KSTEP;
            pa = *(const float4*)(agm + ko);
            pb = *(const float4*)(bgm + ko);
        }
        #pragma unroll
        for (int ks8 = 0; ks8 < 2; ks8++) {
            uint32_t af[2][4];
            uint32_t bf[4][2];
            #pragma unroll
            for (int mt = 0; mt < 2; mt++) {
                int m0 = wm * 32 + mt * 16 + l4;
                const uint32_t* pam = &As[st][m0 * LDP + ks8 * 8 + lk];
                af[mt][0] = pam[0];
                af[mt][1] = pam[8 * LDP];
                af[mt][2] = pam[4];
                af[mt][3] = pam[8 * LDP + 4];
            }
            #pragma unroll
            for (int nt = 0; nt < 4; nt++) {
                int n0 = wn * 32 + nt * 8 + l4;
                const uint32_t* pbm = &Bs[st][n0 * LDP + ks8 * 8 + lk];
                bf[nt][0] = pbm[0];
                bf[nt][1] = pbm[4];
            }
            #pragma unroll
            for (int mt = 0; mt < 2; mt++)
                #pragma unroll
                for (int nt = 0; nt < 4; nt++)
                    mma_tf32(acc[mt][nt], af[mt], bf[nt]);
        }
        if (kc < NKC - 1) {
            int nst = (kc + 1) & 1;
            *(uint4*)&As[nst][sw] = cvt4(pa);
            *(uint4*)&Bs[nst][sw] = cvt4(pb);
        }
        __syncthreads();
    }

    #pragma unroll
    for (int mt = 0; mt < 2; mt++) {
        int r = row0 + wm * 32 + mt * 16 + l4;
        #pragma unroll
        for (int nt = 0; nt < 4; nt++) {
            int cl = wn * 32 + nt * 8 + (lk << 1);
            float bx = sbias[cl], by = sbias[cl + 1];
            float2 v0 = { acc[mt][nt][0] + bx, acc[mt][nt][1] + by };
            float2 v1 = { acc[mt][nt][2] + bx, acc[mt][nt][3] + by };
            *(float2*)&out[(size_t)r * C + col0 + cl]       = v0;
            *(float2*)&out[(size_t)(r + 8) * C + col0 + cl] = v1;
        }
    }
}

// ---------------------------------------------------------------- launch
extern "C" void kernel_launch(void* const* d_in, const int* in_sizes, int n_in,
                              void* d_out, int out_size)
{
    const float* x  = nullptr;
    const float* Wm = nullptr;
    const int*   ei = nullptr;
    const float* b1 = nullptr;
    const float* b2 = nullptr;

    for (int i = 0; i < n_in; i++) {
        int s = in_sizes[i];
        if (s == N_NODES * C)        x  = (const float*)d_in[i];
        else if (s == C * C)         Wm = (const float*)d_in[i];
        else if (s == 2 * 131072)    ei = (const int*)d_in[i];
        else if (s == C) {
            if (!b1) b1 = (const float*)d_in[i];
            else     b2 = (const float*)d_in[i];
        }
    }
    if (!b2) b2 = b1;
    float* out = (float*)d_out;
    int E = 131072;

    k_set_edges<<<(E + 255) / 256, 256>>>(ei, E);
    k_prep<<<N_NODES / ROWS_PER_BLK, 256>>>(x);
    k_spmm<<<N_NODES / 4, 256>>>();
    k_gemm_mma<<<dim3(N_NODES / GT_M, C / GT_N), 512>>>(Wm, b1, b2, out);
}

// round 13
// speedup vs baseline: 1.2452x; 1.2452x over previous
#include <cuda_runtime.h>
#include <cuda_fp16.h>
#include <cstdint>

#define N_NODES 8192
#define C 256
#define NWORDS 256   // 8192 bits / 32 per row
#define MAXDEG 128
#define ROWS_PER_BLK 8

// Scratch (device globals — no allocation allowed)
__device__ unsigned g_bitmap[N_NODES * NWORDS];   // 8 MiB adjacency bitmap (self-cleaning)
__device__ float    g_xs[N_NODES * C];            // dis[j] * x[j]
__device__ float    g_dis[N_NODES];
__device__ float    g_pre[N_NODES * C];           // norm @ x
__device__ int      g_adj[N_NODES * MAXDEG];      // 4 MiB neighbor lists
__device__ int      g_cnt[N_NODES];

// packed fp32x2 add/mul (Blackwell baseline PTX, sm_100+)
#define ADDX2(acc, v) asm("add.rn.f32x2 %0, %0, %1;" : "+l"(acc) : "l"(v))
#define MULX2(acc, v) asm("mul.rn.f32x2 %0, %0, %1;" : "+l"(acc) : "l"(v))
__device__ __forceinline__ unsigned long long d2l(double d) {
    return __double_as_longlong(d);
}

// ---------------------------------------------------------------- K2: edges
__global__ void k_set_edges(const int* __restrict__ ei, int E) {
    int e = blockIdx.x * blockDim.x + threadIdx.x;
    if (e < E) {
        int r = ei[e]     & (N_NODES - 1);
        int c = ei[E + e] & (N_NODES - 1);
        atomicOr(&g_bitmap[r * NWORDS + (c >> 5)], 1u << (c & 31));
    }
}

// ----- K3: prep = degree + decode + prescale + bitmap self-clear (warp/row)
__global__ __launch_bounds__(256) void k_prep(const float* __restrict__ x) {
    int warp = threadIdx.x >> 5;
    int lane = threadIdx.x & 31;
    int row  = blockIdx.x * ROWS_PER_BLK + warp;
    unsigned* bm = &g_bitmap[row * NWORDS];
    unsigned w[8];
    *(uint4*)&w[0] = *(const uint4*)&bm[lane * 8];
    *(uint4*)&w[4] = *(const uint4*)&bm[lane * 8 + 4];
    uint4 z = make_uint4(0u, 0u, 0u, 0u);
    *(uint4*)&bm[lane * 8]     = z;
    *(uint4*)&bm[lane * 8 + 4] = z;

    int cnt = 0;
    #pragma unroll
    for (int q = 0; q < 8; q++) cnt += __popc(w[q]);
    int off = cnt;
    #pragma unroll
    for (int d = 1; d < 32; d <<= 1) {
        int v = __shfl_up_sync(0xFFFFFFFFu, off, d);
        if (lane >= d) off += v;
    }
    int total = __shfl_sync(0xFFFFFFFFu, off, 31);
    off -= cnt;
    int tclamp = total > MAXDEG ? MAXDEG : total;
    if (lane == 0) g_cnt[row] = tclamp;
    int p = off;
    int* adj = &g_adj[row * MAXDEG];
    #pragma unroll
    for (int q = 0; q < 8; q++) {
        unsigned word = w[q];
        while (word) {
            int b = __ffs(word) - 1;
            word &= word - 1;
            if (p < MAXDEG) adj[p] = ((lane * 8 + q) << 5) + b;
            p++;
        }
    }
    float dis = rsqrtf((float)(total + 1));
    if (lane == 0) g_dis[row] = dis;
    int ch = lane * 8;
    float4 v0 = *(const float4*)(x + row * C + ch);
    float4 v1 = *(const float4*)(x + row * C + ch + 4);
    v0.x *= dis; v0.y *= dis; v0.z *= dis; v0.w *= dis;
    v1.x *= dis; v1.y *= dis; v1.z *= dis; v1.w *= dis;
    *(float4*)(g_xs + row * C + ch)     = v0;
    *(float4*)(g_xs + row * C + ch + 4) = v1;
}

// --------------------------------------------------------------- K4: SpMM
__global__ __launch_bounds__(256) void k_spmm() {
    int warp = threadIdx.x >> 5;
    int lane = threadIdx.x & 31;
    int row  = blockIdx.x * 4 + (warp >> 1);
    int ch   = (warp & 1) * 128 + lane * 4;

    int cnt = g_cnt[row];
    const int* adj = &g_adj[row * MAXDEG];
    const float* xs = g_xs;

    double2 e = *(const double2*)(xs + row * C + ch);   // eye term (prescaled)
    unsigned long long acc0 = d2l(e.x);
    unsigned long long acc1 = d2l(e.y);

    int k = 0;
    for (; k + 8 <= cnt; k += 8) {
        int4 ja = *(const int4*)&adj[k];
        int4 jb = *(const int4*)&adj[k + 4];
        double2 v0 = *(const double2*)(xs + ja.x * C + ch);
        double2 v1 = *(const double2*)(xs + ja.y * C + ch);
        double2 v2 = *(const double2*)(xs + ja.z * C + ch);
        double2 v3 = *(const double2*)(xs + ja.w * C + ch);
        double2 v4 = *(const double2*)(xs + jb.x * C + ch);
        double2 v5 = *(const double2*)(xs + jb.y * C + ch);
        double2 v6 = *(const double2*)(xs + jb.z * C + ch);
        double2 v7 = *(const double2*)(xs + jb.w * C + ch);
        ADDX2(acc0, d2l(v0.x)); ADDX2(acc1, d2l(v0.y));
        ADDX2(acc0, d2l(v1.x)); ADDX2(acc1, d2l(v1.y));
        ADDX2(acc0, d2l(v2.x)); ADDX2(acc1, d2l(v2.y));
        ADDX2(acc0, d2l(v3.x)); ADDX2(acc1, d2l(v3.y));
        ADDX2(acc0, d2l(v4.x)); ADDX2(acc1, d2l(v4.y));
        ADDX2(acc0, d2l(v5.x)); ADDX2(acc1, d2l(v5.y));
        ADDX2(acc0, d2l(v6.x)); ADDX2(acc1, d2l(v6.y));
        ADDX2(acc0, d2l(v7.x)); ADDX2(acc1, d2l(v7.y));
    }
    for (; k + 4 <= cnt; k += 4) {
        int4 ja = *(const int4*)&adj[k];
        double2 v0 = *(const double2*)(xs + ja.x * C + ch);
        double2 v1 = *(const double2*)(xs + ja.y * C + ch);
        double2 v2 = *(const double2*)(xs + ja.z * C + ch);
        double2 v3 = *(const double2*)(xs + ja.w * C + ch);
        ADDX2(acc0, d2l(v0.x)); ADDX2(acc1, d2l(v0.y));
        ADDX2(acc0, d2l(v1.x)); ADDX2(acc1, d2l(v1.y));
        ADDX2(acc0, d2l(v2.x)); ADDX2(acc1, d2l(v2.y));
        ADDX2(acc0, d2l(v3.x)); ADDX2(acc1, d2l(v3.y));
    }
    for (; k < cnt; k++) {
        int j = adj[k];
        double2 v = *(const double2*)(xs + j * C + ch);
        ADDX2(acc0, d2l(v.x)); ADDX2(acc1, d2l(v.y));
    }

    float disI = g_dis[row];
    unsigned long long dp;
    asm("mov.b64 %0, {%1, %1};" : "=l"(dp) : "r"(__float_as_uint(disI)));
    MULX2(acc0, dp);
    MULX2(acc1, dp);
    double2 o;
    o.x = __longlong_as_double(acc0);
    o.y = __longlong_as_double(acc1);
    *(double2*)(g_pre + row * C + ch) = o;
}

// ------------------------------------------- K5: fp16 mma.sync GEMM
// out[8192,256] = pre @ W^T + b1 + b2.
// m16n8k16 f16 (2x MACs/instr vs tf32 k8; same 10-bit mantissa).
// CTA tile 128x128, 512 threads / 16 warps (4x4), warp tile 32x32,
// K chunk = 32 floats (2 k-instrs), double-buffered smem.
#define GT_M 128
#define GT_N 128
#define KSTEP 32
#define NKC (C / KSTEP)   // 8
#define LDP 20            // smem row stride in uint32 (16 used + 4 pad); conflict-free

__device__ __forceinline__ uint4 cvt8h(float4 a, float4 b) {
    // 8 floats -> 4 half2 words
    uint4 r;
    __half2 h0 = __floats2half2_rn(a.x, a.y);
    __half2 h1 = __floats2half2_rn(a.z, a.w);
    __half2 h2 = __floats2half2_rn(b.x, b.y);
    __half2 h3 = __floats2half2_rn(b.z, b.w);
    r.x = *(uint32_t*)&h0; r.y = *(uint32_t*)&h1;
    r.z = *(uint32_t*)&h2; r.w = *(uint32_t*)&h3;
    return r;
}
__device__ __forceinline__ void mma_f16(float* c, const uint32_t* a, const uint32_t* b) {
    asm volatile(
        "mma.sync.aligned.m16n8k16.row.col.f32.f16.f16.f32 "
        "{%0,%1,%2,%3}, {%4,%5,%6,%7}, {%8,%9}, {%0,%1,%2,%3};"
        : "+f"(c[0]), "+f"(c[1]), "+f"(c[2]), "+f"(c[3])
        : "r"(a[0]), "r"(a[1]), "r"(a[2]), "r"(a[3]), "r"(b[0]), "r"(b[1]));
}

__global__ __launch_bounds__(512) void k_gemm_mma(
    const float* __restrict__ Wm,
    const float* __restrict__ b1,
    const float* __restrict__ b2,
    float* __restrict__ out)
{
    __shared__ uint32_t As[2][GT_M * LDP];
    __shared__ uint32_t Bs[2][GT_N * LDP];
    __shared__ float sbias[GT_N];

    int tid  = threadIdx.x;
    int wid  = tid >> 5;
    int lane = tid & 31;
    int wm   = wid >> 2;          // 0..3
    int wn   = wid & 3;           // 0..3
    int row0 = blockIdx.x * GT_M;
    int col0 = blockIdx.y * GT_N;

    if (tid < GT_N) sbias[tid] = b1[col0 + tid] + b2[col0 + tid];

    // gmem staging: thread -> row = tid>>2 (0..127), q = tid&3;
    // covers K floats [q*8, q*8+8) of the 32-float chunk -> 4 half2 words.
    int grow = tid >> 2;
    int gq   = tid & 3;
    const float* agm = g_pre + (size_t)(row0 + grow) * C + gq * 8;
    const float* bgm = Wm    + (size_t)(col0 + grow) * C + gq * 8;
    uint32_t sw = grow * LDP + gq * 4;

    float4 pa0 = *(const float4*)(agm);
    float4 pa1 = *(const float4*)(agm + 4);
    float4 pb0 = *(const float4*)(bgm);
    float4 pb1 = *(const float4*)(bgm + 4);
    *(uint4*)&As[0][sw] = cvt8h(pa0, pa1);
    *(uint4*)&Bs[0][sw] = cvt8h(pb0, pb1);
    __syncthreads();

    float acc[2][4][4] = {};
    int l4 = lane >> 2;           // 0..7
    int lk = lane & 3;            // 0..3

    for (int kc = 0; kc < NKC; kc++) {
        int st = kc & 1;
        if (kc < NKC - 1) {
            int ko = (kc + 1) * KSTEP;
            pa0 = *(const float4*)(agm + ko);
            pa1 = *(const float4*)(agm + ko + 4);
            pb0 = *(const float4*)(bgm + ko);
            pb1 = *(const float4*)(bgm + ko + 4);
        }
        #pragma unroll
        for (int ks = 0; ks < 2; ks++) {     // 2 x K=16 fp16 mma per chunk
            uint32_t af[2][4];
            uint32_t bf[4][2];
            #pragma unroll
            for (int mt = 0; mt < 2; mt++) {
                int m0 = wm * 32 + mt * 16 + l4;
                const uint32_t* pam = &As[st][m0 * LDP + ks * 8 + lk];
                af[mt][0] = pam[0];           // row m0,   k 2lk..2lk+1
                af[mt][1] = pam[8 * LDP];     // row m0+8
                af[mt][2] = pam[4];           // row m0,   k 2lk+8..+9
                af[mt][3] = pam[8 * LDP + 4]; // row m0+8
            }
            #pragma unroll
            for (int nt = 0; nt < 4; nt++) {
                int n0 = wn * 32 + nt * 8 + l4;
                const uint32_t* pbm = &Bs[st][n0 * LDP + ks * 8 + lk];
                bf[nt][0] = pbm[0];           // col n0, k 2lk..2lk+1
                bf[nt][1] = pbm[4];           // col n0, k 2lk+8..+9
            }
            #pragma unroll
            for (int mt = 0; mt < 2; mt++)
                #pragma unroll
                for (int nt = 0; nt < 4; nt++)
                    mma_f16(acc[mt][nt], af[mt], bf[nt]);
        }
        if (kc < NKC - 1) {
            int nst = (kc + 1) & 1;
            *(uint4*)&As[nst][sw] = cvt8h(pa0, pa1);
            *(uint4*)&Bs[nst][sw] = cvt8h(pb0, pb1);
        }
        __syncthreads();
    }

    #pragma unroll
    for (int mt = 0; mt < 2; mt++) {
        int r = row0 + wm * 32 + mt * 16 + l4;
        #pragma unroll
        for (int nt = 0; nt < 4; nt++) {
            int cl = wn * 32 + nt * 8 + (lk << 1);
            float bx = sbias[cl], by = sbias[cl + 1];
            float2 v0 = { acc[mt][nt][0] + bx, acc[mt][nt][1] + by };
            float2 v1 = { acc[mt][nt][2] + bx, acc[mt][nt][3] + by };
            *(float2*)&out[(size_t)r * C + col0 + cl]       = v0;
            *(float2*)&out[(size_t)(r + 8) * C + col0 + cl] = v1;
        }
    }
}

// ---------------------------------------------------------------- launch
extern "C" void kernel_launch(void* const* d_in, const int* in_sizes, int n_in,
                              void* d_out, int out_size)
{
    const float* x  = nullptr;
    const float* Wm = nullptr;
    const int*   ei = nullptr;
    const float* b1 = nullptr;
    const float* b2 = nullptr;

    for (int i = 0; i < n_in; i++) {
        int s = in_sizes[i];
        if (s == N_NODES * C)        x  = (const float*)d_in[i];
        else if (s == C * C)         Wm = (const float*)d_in[i];
        else if (s == 2 * 131072)    ei = (const int*)d_in[i];
        else if (s == C) {
            if (!b1) b1 = (const float*)d_in[i];
            else     b2 = (const float*)d_in[i];
        }
    }
    if (!b2) b2 = b1;
    float* out = (float*)d_out;
    int E = 131072;

    k_set_edges<<<(E + 255) / 256, 256>>>(ei, E);
    k_prep<<<N_NODES / ROWS_PER_BLK, 256>>>(x);
    k_spmm<<<N_NODES / 4, 256>>>();
    k_gemm_mma<<<dim3(N_NODES / GT_M, C / GT_N), 512>>>(Wm, b1, b2, out);
}

// round 14
// speedup vs baseline: 1.2464x; 1.0010x over previous
#include <cuda_runtime.h>
#include <cuda_fp16.h>
#include <cstdint>

#define N_NODES 8192
#define C 256
#define NWORDS 256   // 8192 bits / 32 per row
#define MAXDEG 128
#define ROWS_PER_BLK 8
#define ROWV (C / 8) // 32 uint4 (8 halves each) per row

// Scratch (device globals — no allocation allowed)
__device__ unsigned g_bitmap[N_NODES * NWORDS];   // 8 MiB adjacency bitmap (self-cleaning)
__device__ uint4    g_xsh[N_NODES * ROWV];        // 4 MiB: dis[j]*x[j] as half2x4
__device__ float    g_dis[N_NODES];
__device__ uint4    g_preh[N_NODES * ROWV];       // 4 MiB: norm @ x as half2x4
__device__ int      g_adj[N_NODES * MAXDEG];      // 4 MiB neighbor lists
__device__ int      g_cnt[N_NODES];

// ---------------------------------------------------------------- K2: edges
__global__ void k_set_edges(const int* __restrict__ ei, int E) {
    int e = blockIdx.x * blockDim.x + threadIdx.x;
    if (e < E) {
        int r = ei[e]     & (N_NODES - 1);
        int c = ei[E + e] & (N_NODES - 1);
        atomicOr(&g_bitmap[r * NWORDS + (c >> 5)], 1u << (c & 31));
    }
}

__device__ __forceinline__ uint4 pack8h(const float* f) {
    uint4 r;
    __half2 h0 = __floats2half2_rn(f[0], f[1]);
    __half2 h1 = __floats2half2_rn(f[2], f[3]);
    __half2 h2 = __floats2half2_rn(f[4], f[5]);
    __half2 h3 = __floats2half2_rn(f[6], f[7]);
    r.x = *(uint32_t*)&h0; r.y = *(uint32_t*)&h1;
    r.z = *(uint32_t*)&h2; r.w = *(uint32_t*)&h3;
    return r;
}
__device__ __forceinline__ void addh8(float* acc, uint4 v) {
    __half2* h = (__half2*)&v;
    #pragma unroll
    for (int i = 0; i < 4; i++) {
        float2 f = __half22float2(h[i]);
        acc[2 * i]     += f.x;
        acc[2 * i + 1] += f.y;
    }
}

// ----- K3: prep = degree + decode + prescale(fp16) + bitmap self-clear
__global__ __launch_bounds__(256) void k_prep(const float* __restrict__ x) {
    int warp = threadIdx.x >> 5;
    int lane = threadIdx.x & 31;
    int row  = blockIdx.x * ROWS_PER_BLK + warp;
    unsigned* bm = &g_bitmap[row * NWORDS];
    unsigned w[8];
    *(uint4*)&w[0] = *(const uint4*)&bm[lane * 8];
    *(uint4*)&w[4] = *(const uint4*)&bm[lane * 8 + 4];
    uint4 z = make_uint4(0u, 0u, 0u, 0u);
    *(uint4*)&bm[lane * 8]     = z;
    *(uint4*)&bm[lane * 8 + 4] = z;

    int cnt = 0;
    #pragma unroll
    for (int q = 0; q < 8; q++) cnt += __popc(w[q]);
    int off = cnt;
    #pragma unroll
    for (int d = 1; d < 32; d <<= 1) {
        int v = __shfl_up_sync(0xFFFFFFFFu, off, d);
        if (lane >= d) off += v;
    }
    int total = __shfl_sync(0xFFFFFFFFu, off, 31);
    off -= cnt;
    int tclamp = total > MAXDEG ? MAXDEG : total;
    if (lane == 0) g_cnt[row] = tclamp;
    int p = off;
    int* adj = &g_adj[row * MAXDEG];
    #pragma unroll
    for (int q = 0; q < 8; q++) {
        unsigned word = w[q];
        while (word) {
            int b = __ffs(word) - 1;
            word &= word - 1;
            if (p < MAXDEG) adj[p] = ((lane * 8 + q) << 5) + b;
            p++;
        }
    }
    float dis = rsqrtf((float)(total + 1));
    if (lane == 0) g_dis[row] = dis;
    int ch = lane * 8;
    float4 v0 = *(const float4*)(x + row * C + ch);
    float4 v1 = *(const float4*)(x + row * C + ch + 4);
    float f[8] = { v0.x * dis, v0.y * dis, v0.z * dis, v0.w * dis,
                   v1.x * dis, v1.y * dis, v1.z * dis, v1.w * dis };
    g_xsh[row * ROWV + lane] = pack8h(f);
}

// --------------------------------------------------------------- K4: SpMM
// One warp per row; lane owns 8 channels (one 16B half8 vector).
// pre[i] = dis_i * ( xs_i + sum_j xs_j ), fp32 accumulate, fp16 store.
__global__ __launch_bounds__(256) void k_spmm() {
    int warp = threadIdx.x >> 5;
    int lane = threadIdx.x & 31;
    int row  = blockIdx.x * 8 + warp;

    int cnt = g_cnt[row];
    const int* adj = &g_adj[row * MAXDEG];
    const uint4* xs = g_xsh;

    float acc[8] = {};
    addh8(acc, xs[row * ROWV + lane]);            // eye term (prescaled)

    int k = 0;
    for (; k + 8 <= cnt; k += 8) {
        int4 ja = *(const int4*)&adj[k];
        int4 jb = *(const int4*)&adj[k + 4];
        uint4 v0 = xs[ja.x * ROWV + lane];
        uint4 v1 = xs[ja.y * ROWV + lane];
        uint4 v2 = xs[ja.z * ROWV + lane];
        uint4 v3 = xs[ja.w * ROWV + lane];
        uint4 v4 = xs[jb.x * ROWV + lane];
        uint4 v5 = xs[jb.y * ROWV + lane];
        uint4 v6 = xs[jb.z * ROWV + lane];
        uint4 v7 = xs[jb.w * ROWV + lane];
        addh8(acc, v0); addh8(acc, v1); addh8(acc, v2); addh8(acc, v3);
        addh8(acc, v4); addh8(acc, v5); addh8(acc, v6); addh8(acc, v7);
    }
    for (; k + 4 <= cnt; k += 4) {
        int4 ja = *(const int4*)&adj[k];
        uint4 v0 = xs[ja.x * ROWV + lane];
        uint4 v1 = xs[ja.y * ROWV + lane];
        uint4 v2 = xs[ja.z * ROWV + lane];
        uint4 v3 = xs[ja.w * ROWV + lane];
        addh8(acc, v0); addh8(acc, v1); addh8(acc, v2); addh8(acc, v3);
    }
    for (; k < cnt; k++) {
        uint4 v = xs[adj[k] * ROWV + lane];
        addh8(acc, v);
    }

    float disI = g_dis[row];
    #pragma unroll
    for (int i = 0; i < 8; i++) acc[i] *= disI;
    g_preh[row * ROWV + lane] = pack8h(acc);
}

// ------------------------------------------- K5: fp16 mma.sync GEMM
// out[8192,256] = pre @ W^T + b1 + b2.  A already fp16-packed (g_preh).
// CTA tile 128x128, 512 threads / 16 warps (4x4), warp tile 32x32,
// K chunk = 32 (2 k16 mma steps), double-buffered smem.
#define GT_M 128
#define GT_N 128
#define KSTEP 32
#define NKC (C / KSTEP)   // 8
#define LDP 20            // smem row stride in uint32; conflict-free

__device__ __forceinline__ uint4 cvt8h(float4 a, float4 b) {
    uint4 r;
    __half2 h0 = __floats2half2_rn(a.x, a.y);
    __half2 h1 = __floats2half2_rn(a.z, a.w);
    __half2 h2 = __floats2half2_rn(b.x, b.y);
    __half2 h3 = __floats2half2_rn(b.z, b.w);
    r.x = *(uint32_t*)&h0; r.y = *(uint32_t*)&h1;
    r.z = *(uint32_t*)&h2; r.w = *(uint32_t*)&h3;
    return r;
}
__device__ __forceinline__ void mma_f16(float* c, const uint32_t* a, const uint32_t* b) {
    asm volatile(
        "mma.sync.aligned.m16n8k16.row.col.f32.f16.f16.f32 "
        "{%0,%1,%2,%3}, {%4,%5,%6,%7}, {%8,%9}, {%0,%1,%2,%3};"
        : "+f"(c[0]), "+f"(c[1]), "+f"(c[2]), "+f"(c[3])
        : "r"(a[0]), "r"(a[1]), "r"(a[2]), "r"(a[3]), "r"(b[0]), "r"(b[1]));
}

__global__ __launch_bounds__(512) void k_gemm_mma(
    const float* __restrict__ Wm,
    const float* __restrict__ b1,
    const float* __restrict__ b2,
    float* __restrict__ out)
{
    __shared__ uint32_t As[2][GT_M * LDP];
    __shared__ uint32_t Bs[2][GT_N * LDP];
    __shared__ float sbias[GT_N];

    int tid  = threadIdx.x;
    int wid  = tid >> 5;
    int lane = tid & 31;
    int wm   = wid >> 2;          // 0..3
    int wn   = wid & 3;           // 0..3
    int row0 = blockIdx.x * GT_M;
    int col0 = blockIdx.y * GT_N;

    if (tid < GT_N) sbias[tid] = b1[col0 + tid] + b2[col0 + tid];

    // staging: thread -> row = tid>>2, q = tid&3 -> K halves [q*8, q*8+8)
    int grow = tid >> 2;
    int gq   = tid & 3;
    const uint4*  agm = g_preh + (size_t)(row0 + grow) * ROWV + gq;  // +kc*4 per chunk
    const float*  bgm = Wm     + (size_t)(col0 + grow) * C + gq * 8;
    uint32_t sw = grow * LDP + gq * 4;

    uint4  paq = agm[0];
    float4 pb0 = *(const float4*)(bgm);
    float4 pb1 = *(const float4*)(bgm + 4);
    *(uint4*)&As[0][sw] = paq;
    *(uint4*)&Bs[0][sw] = cvt8h(pb0, pb1);
    __syncthreads();

    float acc[2][4][4] = {};
    int l4 = lane >> 2;           // 0..7
    int lk = lane & 3;            // 0..3

    for (int kc = 0; kc < NKC; kc++) {
        int st = kc & 1;
        if (kc < NKC - 1) {
            int ko = (kc + 1) * KSTEP;
            paq = agm[(kc + 1) * 4];
            pb0 = *(const float4*)(bgm + ko);
            pb1 = *(const float4*)(bgm + ko + 4);
        }
        #pragma unroll
        for (int ks = 0; ks < 2; ks++) {     // 2 x K=16 fp16 mma per chunk
            uint32_t af[2][4];
            uint32_t bf[4][2];
            #pragma unroll
            for (int mt = 0; mt < 2; mt++) {
                int m0 = wm * 32 + mt * 16 + l4;
                const uint32_t* pam = &As[st][m0 * LDP + ks * 8 + lk];
                af[mt][0] = pam[0];
                af[mt][1] = pam[8 * LDP];
                af[mt][2] = pam[4];
                af[mt][3] = pam[8 * LDP + 4];
            }
            #pragma unroll
            for (int nt = 0; nt < 4; nt++) {
                int n0 = wn * 32 + nt * 8 + l4;
                const uint32_t* pbm = &Bs[st][n0 * LDP + ks * 8 + lk];
                bf[nt][0] = pbm[0];
                bf[nt][1] = pbm[4];
            }
            #pragma unroll
            for (int mt = 0; mt < 2; mt++)
                #pragma unroll
                for (int nt = 0; nt < 4; nt++)
                    mma_f16(acc[mt][nt], af[mt], bf[nt]);
        }
        if (kc < NKC - 1) {
            int nst = (kc + 1) & 1;
            *(uint4*)&As[nst][sw] = paq;
            *(uint4*)&Bs[nst][sw] = cvt8h(pb0, pb1);
        }
        __syncthreads();
    }

    #pragma unroll
    for (int mt = 0; mt < 2; mt++) {
        int r = row0 + wm * 32 + mt * 16 + l4;
        #pragma unroll
        for (int nt = 0; nt < 4; nt++) {
            int cl = wn * 32 + nt * 8 + (lk << 1);
            float bx = sbias[cl], by = sbias[cl + 1];
            float2 v0 = { acc[mt][nt][0] + bx, acc[mt][nt][1] + by };
            float2 v1 = { acc[mt][nt][2] + bx, acc[mt][nt][3] + by };
            *(float2*)&out[(size_t)r * C + col0 + cl]       = v0;
            *(float2*)&out[(size_t)(r + 8) * C + col0 + cl] = v1;
        }
    }
}

// ---------------------------------------------------------------- launch
extern "C" void kernel_launch(void* const* d_in, const int* in_sizes, int n_in,
                              void* d_out, int out_size)
{
    const float* x  = nullptr;
    const float* Wm = nullptr;
    const int*   ei = nullptr;
    const float* b1 = nullptr;
    const float* b2 = nullptr;

    for (int i = 0; i < n_in; i++) {
        int s = in_sizes[i];
        if (s == N_NODES * C)        x  = (const float*)d_in[i];
        else if (s == C * C)         Wm = (const float*)d_in[i];
        else if (s == 2 * 131072)    ei = (const int*)d_in[i];
        else if (s == C) {
            if (!b1) b1 = (const float*)d_in[i];
            else     b2 = (const float*)d_in[i];
        }
    }
    if (!b2) b2 = b1;
    float* out = (float*)d_out;
    int E = 131072;

    k_set_edges<<<(E + 255) / 256, 256>>>(ei, E);
    k_prep<<<N_NODES / ROWS_PER_BLK, 256>>>(x);
    k_spmm<<<N_NODES / 8, 256>>>();
    k_gemm_mma<<<dim3(N_NODES / GT_M, C / GT_N), 512>>>(Wm, b1, b2, out);
}

// round 15
// speedup vs baseline: 1.3434x; 1.0778x over previous
#include <cuda_runtime.h>
#include <cuda_fp16.h>
#include <cstdint>

#define N_NODES 8192
#define C 256
#define NWORDS 256   // 8192 bits / 32 per row
#define MAXDEG 128
#define ROWS_PER_BLK 8
#define ROWV (C / 8) // 32 uint4 (8 halves each) per row

// Scratch (device globals — no allocation allowed)
__device__ unsigned g_bitmap[N_NODES * NWORDS];   // 8 MiB adjacency bitmap (self-cleaning)
__device__ uint4    g_xsh[N_NODES * ROWV];        // 4 MiB: dis[j]*x[j] as half2x4
__device__ float    g_dis[N_NODES];
__device__ uint4    g_preh[N_NODES * ROWV];       // 4 MiB: norm @ x as half2x4
__device__ uint4    g_wh[C * ROWV];               // 128 KiB: W as fp16
__device__ int      g_adj[N_NODES * MAXDEG];      // 4 MiB neighbor lists
__device__ int      g_cnt[N_NODES];

// ------------------------------------------- K2: edges + W fp16 convert
__global__ void k_set_edges(const int* __restrict__ ei, int E,
                            const float* __restrict__ Wm) {
    int e = blockIdx.x * blockDim.x + threadIdx.x;
    if (e < E) {
        int r = ei[e]     & (N_NODES - 1);
        int c = ei[E + e] & (N_NODES - 1);
        atomicOr(&g_bitmap[r * NWORDS + (c >> 5)], 1u << (c & 31));
    }
    if (e < C * C / 2) {               // 32768 threads pack W -> fp16
        float2 w = ((const float2*)Wm)[e];
        __half2 h = __floats2half2_rn(w.x, w.y);
        ((uint32_t*)g_wh)[e] = *(uint32_t*)&h;
    }
}

__device__ __forceinline__ uint4 pack8h(const float* f) {
    uint4 r;
    __half2 h0 = __floats2half2_rn(f[0], f[1]);
    __half2 h1 = __floats2half2_rn(f[2], f[3]);
    __half2 h2 = __floats2half2_rn(f[4], f[5]);
    __half2 h3 = __floats2half2_rn(f[6], f[7]);
    r.x = *(uint32_t*)&h0; r.y = *(uint32_t*)&h1;
    r.z = *(uint32_t*)&h2; r.w = *(uint32_t*)&h3;
    return r;
}
__device__ __forceinline__ void addh8(float* acc, uint4 v) {
    __half2* h = (__half2*)&v;
    #pragma unroll
    for (int i = 0; i < 4; i++) {
        float2 f = __half22float2(h[i]);
        acc[2 * i]     += f.x;
        acc[2 * i + 1] += f.y;
    }
}

// ----- K3: prep = degree + decode + prescale(fp16) + bitmap self-clear
__global__ __launch_bounds__(256) void k_prep(const float* __restrict__ x) {
    int warp = threadIdx.x >> 5;
    int lane = threadIdx.x & 31;
    int row  = blockIdx.x * ROWS_PER_BLK + warp;
    unsigned* bm = &g_bitmap[row * NWORDS];
    unsigned w[8];
    *(uint4*)&w[0] = *(const uint4*)&bm[lane * 8];
    *(uint4*)&w[4] = *(const uint4*)&bm[lane * 8 + 4];
    uint4 z = make_uint4(0u, 0u, 0u, 0u);
    *(uint4*)&bm[lane * 8]     = z;
    *(uint4*)&bm[lane * 8 + 4] = z;

    int cnt = 0;
    #pragma unroll
    for (int q = 0; q < 8; q++) cnt += __popc(w[q]);
    int off = cnt;
    #pragma unroll
    for (int d = 1; d < 32; d <<= 1) {
        int v = __shfl_up_sync(0xFFFFFFFFu, off, d);
        if (lane >= d) off += v;
    }
    int total = __shfl_sync(0xFFFFFFFFu, off, 31);
    off -= cnt;
    int tclamp = total > MAXDEG ? MAXDEG : total;
    if (lane == 0) g_cnt[row] = tclamp;
    int p = off;
    int* adj = &g_adj[row * MAXDEG];
    #pragma unroll
    for (int q = 0; q < 8; q++) {
        unsigned word = w[q];
        while (word) {
            int b = __ffs(word) - 1;
            word &= word - 1;
            if (p < MAXDEG) adj[p] = ((lane * 8 + q) << 5) + b;
            p++;
        }
    }
    float dis = rsqrtf((float)(total + 1));
    if (lane == 0) g_dis[row] = dis;
    int ch = lane * 8;
    float4 v0 = *(const float4*)(x + row * C + ch);
    float4 v1 = *(const float4*)(x + row * C + ch + 4);
    float f[8] = { v0.x * dis, v0.y * dis, v0.z * dis, v0.w * dis,
                   v1.x * dis, v1.y * dis, v1.z * dis, v1.w * dis };
    g_xsh[row * ROWV + lane] = pack8h(f);
}

// --------------------------------------------------------------- K4: SpMM
__global__ __launch_bounds__(256) void k_spmm() {
    int warp = threadIdx.x >> 5;
    int lane = threadIdx.x & 31;
    int row  = blockIdx.x * 8 + warp;

    int cnt = g_cnt[row];
    const int* adj = &g_adj[row * MAXDEG];
    const uint4* xs = g_xsh;

    float acc[8] = {};
    addh8(acc, xs[row * ROWV + lane]);            // eye term (prescaled)

    int k = 0;
    for (; k + 8 <= cnt; k += 8) {
        int4 ja = *(const int4*)&adj[k];
        int4 jb = *(const int4*)&adj[k + 4];
        uint4 v0 = xs[ja.x * ROWV + lane];
        uint4 v1 = xs[ja.y * ROWV + lane];
        uint4 v2 = xs[ja.z * ROWV + lane];
        uint4 v3 = xs[ja.w * ROWV + lane];
        uint4 v4 = xs[jb.x * ROWV + lane];
        uint4 v5 = xs[jb.y * ROWV + lane];
        uint4 v6 = xs[jb.z * ROWV + lane];
        uint4 v7 = xs[jb.w * ROWV + lane];
        addh8(acc, v0); addh8(acc, v1); addh8(acc, v2); addh8(acc, v3);
        addh8(acc, v4); addh8(acc, v5); addh8(acc, v6); addh8(acc, v7);
    }
    for (; k + 4 <= cnt; k += 4) {
        int4 ja = *(const int4*)&adj[k];
        uint4 v0 = xs[ja.x * ROWV + lane];
        uint4 v1 = xs[ja.y * ROWV + lane];
        uint4 v2 = xs[ja.z * ROWV + lane];
        uint4 v3 = xs[ja.w * ROWV + lane];
        addh8(acc, v0); addh8(acc, v1); addh8(acc, v2); addh8(acc, v3);
    }
    for (; k < cnt; k++) {
        uint4 v = xs[adj[k] * ROWV + lane];
        addh8(acc, v);
    }

    float disI = g_dis[row];
    #pragma unroll
    for (int i = 0; i < 8; i++) acc[i] *= disI;
    g_preh[row * ROWV + lane] = pack8h(acc);
}

// ------------------------------------------- K5: fp16 mma, full-K resident
// out[8192,256] = pre @ W^T + b1 + b2.
// CTA tile 128x128; BOTH tiles staged whole (K=256) via cp.async.cg;
// single barrier; then 128 barrier-free m16n8k16 per warp.
#define GT_M 128
#define GT_N 128
#define LDW 132                  // padded row stride in words (128 + 4)
#define ASIZE (GT_M * LDW)       // words per tile
#define SMEM_BYTES (2 * ASIZE * 4)

__device__ __forceinline__ void mma_f16(float* c, const uint32_t* a, const uint32_t* b) {
    asm volatile(
        "mma.sync.aligned.m16n8k16.row.col.f32.f16.f16.f32 "
        "{%0,%1,%2,%3}, {%4,%5,%6,%7}, {%8,%9}, {%0,%1,%2,%3};"
        : "+f"(c[0]), "+f"(c[1]), "+f"(c[2]), "+f"(c[3])
        : "r"(a[0]), "r"(a[1]), "r"(a[2]), "r"(a[3]), "r"(b[0]), "r"(b[1]));
}
__device__ __forceinline__ uint32_t smem_u32(const void* p) {
    uint32_t a;
    asm("{ .reg .u64 t; cvta.to.shared.u64 t, %1; cvt.u32.u64 %0, t; }"
        : "=r"(a) : "l"(p));
    return a;
}
#define CP_ASYNC16(dst, src) \
    asm volatile("cp.async.cg.shared.global [%0], [%1], 16;" \
                 :: "r"(dst), "l"(src) : "memory")

__global__ __launch_bounds__(512) void k_gemm_mma(
    const float* __restrict__ b1,
    const float* __restrict__ b2,
    float* __restrict__ out)
{
    extern __shared__ uint32_t sm[];
    uint32_t* As = sm;
    uint32_t* Bs = sm + ASIZE;
    __shared__ float sbias[GT_N];

    int tid  = threadIdx.x;
    int wid  = tid >> 5;
    int lane = tid & 31;
    int wm   = wid >> 2;          // 0..3
    int wn   = wid & 3;           // 0..3
    int row0 = blockIdx.x * GT_M;
    int col0 = blockIdx.y * GT_N;

    uint32_t abase = smem_u32(As);
    uint32_t bbase = smem_u32(Bs);

    // stage whole tiles: 128 rows x 32 x 16B each, 8 iters of 512 threads
    #pragma unroll
    for (int it = 0; it < 8; it++) {
        int idx = tid + it * 512;        // 0..4095
        int r = idx >> 5, c4 = idx & 31;
        uint32_t da = abase + (r * LDW + c4 * 4) * 4;
        CP_ASYNC16(da, g_preh + (size_t)(row0 + r) * ROWV + c4);
        uint32_t db = bbase + (r * LDW + c4 * 4) * 4;
        CP_ASYNC16(db, g_wh + (size_t)(col0 + r) * ROWV + c4);
    }
    asm volatile("cp.async.commit_group;" ::: "memory");

    if (tid < GT_N) sbias[tid] = b1[col0 + tid] + b2[col0 + tid];

    asm volatile("cp.async.wait_group 0;" ::: "memory");
    __syncthreads();

    float acc[2][4][4] = {};
    int l4 = lane >> 2;           // 0..7
    int lk = lane & 3;            // 0..3

    #pragma unroll
    for (int ks = 0; ks < 16; ks++) {      // 16 x K=16 steps, no barriers
        uint32_t af[2][4];
        uint32_t bf[4][2];
        #pragma unroll
        for (int mt = 0; mt < 2; mt++) {
            int m0 = wm * 32 + mt * 16 + l4;
            const uint32_t* pam = &As[m0 * LDW + ks * 8 + lk];
            af[mt][0] = pam[0];
            af[mt][1] = pam[8 * LDW];
            af[mt][2] = pam[4];
            af[mt][3] = pam[8 * LDW + 4];
        }
        #pragma unroll
        for (int nt = 0; nt < 4; nt++) {
            int n0 = wn * 32 + nt * 8 + l4;
            const uint32_t* pbm = &Bs[n0 * LDW + ks * 8 + lk];
            bf[nt][0] = pbm[0];
            bf[nt][1] = pbm[4];
        }
        #pragma unroll
        for (int mt = 0; mt < 2; mt++)
            #pragma unroll
            for (int nt = 0; nt < 4; nt++)
                mma_f16(acc[mt][nt], af[mt], bf[nt]);
    }

    #pragma unroll
    for (int mt = 0; mt < 2; mt++) {
        int r = row0 + wm * 32 + mt * 16 + l4;
        #pragma unroll
        for (int nt = 0; nt < 4; nt++) {
            int cl = wn * 32 + nt * 8 + (lk << 1);
            float bx = sbias[cl], by = sbias[cl + 1];
            float2 v0 = { acc[mt][nt][0] + bx, acc[mt][nt][1] + by };
            float2 v1 = { acc[mt][nt][2] + bx, acc[mt][nt][3] + by };
            *(float2*)&out[(size_t)r * C + col0 + cl]       = v0;
            *(float2*)&out[(size_t)(r + 8) * C + col0 + cl] = v1;
        }
    }
}

// ---------------------------------------------------------------- launch
extern "C" void kernel_launch(void* const* d_in, const int* in_sizes, int n_in,
                              void* d_out, int out_size)
{
    const float* x  = nullptr;
    const float* Wm = nullptr;
    const int*   ei = nullptr;
    const float* b1 = nullptr;
    const float* b2 = nullptr;

    for (int i = 0; i < n_in; i++) {
        int s = in_sizes[i];
        if (s == N_NODES * C)        x  = (const float*)d_in[i];
        else if (s == C * C)         Wm = (const float*)d_in[i];
        else if (s == 2 * 131072)    ei = (const int*)d_in[i];
        else if (s == C) {
            if (!b1) b1 = (const float*)d_in[i];
            else     b2 = (const float*)d_in[i];
        }
    }
    if (!b2) b2 = b1;
    float* out = (float*)d_out;
    int E = 131072;

    static bool attr_done = false;
    if (!attr_done) {   // first call is the (uncaptured) correctness run
        cudaFuncSetAttribute(k_gemm_mma,
                             cudaFuncAttributeMaxDynamicSharedMemorySize,
                             SMEM_BYTES);
        attr_done = true;
    }

    k_set_edges<<<(E + 255) / 256, 256>>>(ei, E, Wm);
    k_prep<<<N_NODES / ROWS_PER_BLK, 256>>>(x);
    k_spmm<<<N_NODES / 8, 256>>>();
    k_gemm_mma<<<dim3(N_NODES / GT_M, C / GT_N), 512, SMEM_BYTES>>>(b1, b2, out);
}

// round 16
// speedup vs baseline: 1.4200x; 1.0570x over previous
#include <cuda_runtime.h>
#include <cuda_fp16.h>
#include <cstdint>

#define N_NODES 8192
#define C 256
#define NWORDS 256   // 8192 bits / 32 per row
#define MAXDEG 128
#define ROWS_PER_BLK 8
#define ROWV (C / 8) // 32 uint4 (8 halves each) per row

// Scratch (device globals — no allocation allowed)
__device__ unsigned g_bitmap[N_NODES * NWORDS];   // 8 MiB adjacency bitmap (self-cleaning)
__device__ uint4    g_xsh[N_NODES * ROWV];        // 4 MiB: dis[j]*x[j] as half2x4
__device__ float    g_dis[N_NODES];
__device__ uint4    g_preh[N_NODES * ROWV];       // 4 MiB: norm @ x as half2x4
__device__ uint4    g_wh[C * ROWV];               // 128 KiB: W as fp16
__device__ int      g_adj[N_NODES * MAXDEG];      // 4 MiB neighbor lists
__device__ int      g_cnt[N_NODES];

// ------------------------------------------- K2: edges + W fp16 convert
__global__ void k_set_edges(const int* __restrict__ ei, int E,
                            const float* __restrict__ Wm) {
    int e = blockIdx.x * blockDim.x + threadIdx.x;
    if (e < E) {
        int r = ei[e]     & (N_NODES - 1);
        int c = ei[E + e] & (N_NODES - 1);
        atomicOr(&g_bitmap[r * NWORDS + (c >> 5)], 1u << (c & 31));
    }
    if (e < C * C / 2) {               // 32768 threads pack W -> fp16
        float2 w = ((const float2*)Wm)[e];
        __half2 h = __floats2half2_rn(w.x, w.y);
        ((uint32_t*)g_wh)[e] = *(uint32_t*)&h;
    }
}

__device__ __forceinline__ uint4 pack8h(const float* f) {
    uint4 r;
    __half2 h0 = __floats2half2_rn(f[0], f[1]);
    __half2 h1 = __floats2half2_rn(f[2], f[3]);
    __half2 h2 = __floats2half2_rn(f[4], f[5]);
    __half2 h3 = __floats2half2_rn(f[6], f[7]);
    r.x = *(uint32_t*)&h0; r.y = *(uint32_t*)&h1;
    r.z = *(uint32_t*)&h2; r.w = *(uint32_t*)&h3;
    return r;
}
__device__ __forceinline__ void addh8(float* acc, uint4 v) {
    __half2* h = (__half2*)&v;
    #pragma unroll
    for (int i = 0; i < 4; i++) {
        float2 f = __half22float2(h[i]);
        acc[2 * i]     += f.x;
        acc[2 * i + 1] += f.y;
    }
}

// ----- K3: prep = degree + decode + prescale(fp16) + bitmap self-clear
__global__ __launch_bounds__(256) void k_prep(const float* __restrict__ x) {
    int warp = threadIdx.x >> 5;
    int lane = threadIdx.x & 31;
    int row  = blockIdx.x * ROWS_PER_BLK + warp;
    unsigned* bm = &g_bitmap[row * NWORDS];
    unsigned w[8];
    *(uint4*)&w[0] = *(const uint4*)&bm[lane * 8];
    *(uint4*)&w[4] = *(const uint4*)&bm[lane * 8 + 4];
    uint4 z = make_uint4(0u, 0u, 0u, 0u);
    *(uint4*)&bm[lane * 8]     = z;
    *(uint4*)&bm[lane * 8 + 4] = z;

    int cnt = 0;
    #pragma unroll
    for (int q = 0; q < 8; q++) cnt += __popc(w[q]);
    int off = cnt;
    #pragma unroll
    for (int d = 1; d < 32; d <<= 1) {
        int v = __shfl_up_sync(0xFFFFFFFFu, off, d);
        if (lane >= d) off += v;
    }
    int total = __shfl_sync(0xFFFFFFFFu, off, 31);
    off -= cnt;
    int tclamp = total > MAXDEG ? MAXDEG : total;
    if (lane == 0) g_cnt[row] = tclamp;
    int p = off;
    int* adj = &g_adj[row * MAXDEG];
    #pragma unroll
    for (int q = 0; q < 8; q++) {
        unsigned word = w[q];
        while (word) {
            int b = __ffs(word) - 1;
            word &= word - 1;
            if (p < MAXDEG) adj[p] = ((lane * 8 + q) << 5) + b;
            p++;
        }
    }
    float dis = rsqrtf((float)(total + 1));
    if (lane == 0) g_dis[row] = dis;
    int ch = lane * 8;
    float4 v0 = *(const float4*)(x + row * C + ch);
    float4 v1 = *(const float4*)(x + row * C + ch + 4);
    float f[8] = { v0.x * dis, v0.y * dis, v0.z * dis, v0.w * dis,
                   v1.x * dis, v1.y * dis, v1.z * dis, v1.w * dis };
    g_xsh[row * ROWV + lane] = pack8h(f);
}

// --------------------------------------------------------------- K4: SpMM
__global__ __launch_bounds__(256) void k_spmm() {
    int warp = threadIdx.x >> 5;
    int lane = threadIdx.x & 31;
    int row  = blockIdx.x * 8 + warp;

    int cnt = g_cnt[row];
    const int* adj = &g_adj[row * MAXDEG];
    const uint4* xs = g_xsh;

    float acc[8] = {};
    addh8(acc, xs[row * ROWV + lane]);            // eye term (prescaled)

    int k = 0;
    for (; k + 8 <= cnt; k += 8) {
        int4 ja = *(const int4*)&adj[k];
        int4 jb = *(const int4*)&adj[k + 4];
        uint4 v0 = xs[ja.x * ROWV + lane];
        uint4 v1 = xs[ja.y * ROWV + lane];
        uint4 v2 = xs[ja.z * ROWV + lane];
        uint4 v3 = xs[ja.w * ROWV + lane];
        uint4 v4 = xs[jb.x * ROWV + lane];
        uint4 v5 = xs[jb.y * ROWV + lane];
        uint4 v6 = xs[jb.z * ROWV + lane];
        uint4 v7 = xs[jb.w * ROWV + lane];
        addh8(acc, v0); addh8(acc, v1); addh8(acc, v2); addh8(acc, v3);
        addh8(acc, v4); addh8(acc, v5); addh8(acc, v6); addh8(acc, v7);
    }
    for (; k + 4 <= cnt; k += 4) {
        int4 ja = *(const int4*)&adj[k];
        uint4 v0 = xs[ja.x * ROWV + lane];
        uint4 v1 = xs[ja.y * ROWV + lane];
        uint4 v2 = xs[ja.z * ROWV + lane];
        uint4 v3 = xs[ja.w * ROWV + lane];
        addh8(acc, v0); addh8(acc, v1); addh8(acc, v2); addh8(acc, v3);
    }
    for (; k < cnt; k++) {
        uint4 v = xs[adj[k] * ROWV + lane];
        addh8(acc, v);
    }

    float disI = g_dis[row];
    #pragma unroll
    for (int i = 0; i < 8; i++) acc[i] *= disI;
    g_preh[row * ROWV + lane] = pack8h(acc);
}

// ------------------------------------------- K5: fp16 mma, full-K resident
// out[8192,256] = pre @ W^T + b1 + b2.
// CTA tile 128x128; both tiles staged whole via cp.async; single barrier;
// mainloop: ldmatrix.x4 fragment loads + register double-buffering.
#define GT_M 128
#define GT_N 128
#define LDW 132                  // padded row stride in words (128 + 4)
#define ASIZE (GT_M * LDW)
#define SMEM_BYTES (2 * ASIZE * 4)

__device__ __forceinline__ void mma_f16(float* c, const uint32_t* a, const uint32_t* b) {
    asm volatile(
        "mma.sync.aligned.m16n8k16.row.col.f32.f16.f16.f32 "
        "{%0,%1,%2,%3}, {%4,%5,%6,%7}, {%8,%9}, {%0,%1,%2,%3};"
        : "+f"(c[0]), "+f"(c[1]), "+f"(c[2]), "+f"(c[3])
        : "r"(a[0]), "r"(a[1]), "r"(a[2]), "r"(a[3]), "r"(b[0]), "r"(b[1]));
}
__device__ __forceinline__ uint32_t smem_u32(const void* p) {
    uint32_t a;
    asm("{ .reg .u64 t; cvta.to.shared.u64 t, %1; cvt.u32.u64 %0, t; }"
        : "=r"(a) : "l"(p));
    return a;
}
#define CP_ASYNC16(dst, src) \
    asm volatile("cp.async.cg.shared.global [%0], [%1], 16;" \
                 :: "r"(dst), "l"(src) : "memory")
#define LDSM4(r, addr) \
    asm volatile("ldmatrix.sync.aligned.m8n8.x4.shared.b16 {%0,%1,%2,%3}, [%4];" \
                 : "=r"((r)[0]), "=r"((r)[1]), "=r"((r)[2]), "=r"((r)[3]) : "r"(addr))

__global__ __launch_bounds__(512) void k_gemm_mma(
    const float* __restrict__ b1,
    const float* __restrict__ b2,
    float* __restrict__ out)
{
    extern __shared__ uint32_t sm[];
    uint32_t* As = sm;
    uint32_t* Bs = sm + ASIZE;
    __shared__ float sbias[GT_N];

    int tid  = threadIdx.x;
    int wid  = tid >> 5;
    int lane = tid & 31;
    int wm   = wid >> 2;          // 0..3
    int wn   = wid & 3;           // 0..3
    int row0 = blockIdx.x * GT_M;
    int col0 = blockIdx.y * GT_N;

    uint32_t abase = smem_u32(As);
    uint32_t bbase = smem_u32(Bs);

    // stage whole tiles (K=256): 128 rows x 32 x 16B each
    #pragma unroll
    for (int it = 0; it < 8; it++) {
        int idx = tid + it * 512;        // 0..4095
        int r = idx >> 5, c4 = idx & 31;
        uint32_t da = abase + (r * LDW + c4 * 4) * 4;
        CP_ASYNC16(da, g_preh + (size_t)(row0 + r) * ROWV + c4);
        uint32_t db = bbase + (r * LDW + c4 * 4) * 4;
        CP_ASYNC16(db, g_wh + (size_t)(col0 + r) * ROWV + c4);
    }
    asm volatile("cp.async.commit_group;" ::: "memory");

    if (tid < GT_N) sbias[tid] = b1[col0 + tid] + b2[col0 + tid];

    asm volatile("cp.async.wait_group 0;" ::: "memory");
    __syncthreads();

    // ldmatrix per-lane addresses
    int grp = lane >> 3;          // matrix id 0..3
    int rr  = lane & 7;
    // A x4 order: [m0 k0], [m8 k0], [m0 k8], [m8 k8]
    int arow = (grp & 1) * 8 + rr;
    int akw  = (grp >> 1) * 4;
    uint32_t aaddr0 = abase + ((wm * 32 +      arow) * LDW + akw) * 4;
    uint32_t aaddr1 = abase + ((wm * 32 + 16 + arow) * LDW + akw) * 4;
    // B x4 order: [n0 k0], [n0 k8], [n8 k0], [n8 k8]
    int brow = (grp >> 1) * 8 + rr;
    int bkw  = (grp & 1) * 4;
    uint32_t baddr0 = bbase + ((wn * 32 +      brow) * LDW + bkw) * 4;
    uint32_t baddr1 = bbase + ((wn * 32 + 16 + brow) * LDW + bkw) * 4;

    float acc[2][4][4] = {};
    uint32_t af[2][2][4];   // [buf][mt][4]
    uint32_t bf[2][2][4];   // [buf][ntp][4] = {b0(nt), b1(nt), b0(nt+1), b1(nt+1)}

    LDSM4(af[0][0], aaddr0);
    LDSM4(af[0][1], aaddr1);
    LDSM4(bf[0][0], baddr0);
    LDSM4(bf[0][1], baddr1);

    #pragma unroll
    for (int ks = 0; ks < 16; ks++) {
        int cur = ks & 1;
        if (ks < 15) {
            int nxt = cur ^ 1;
            uint32_t ko = (ks + 1) * 32;   // 8 words = 32 bytes per K16 step
            LDSM4(af[nxt][0], aaddr0 + ko);
            LDSM4(af[nxt][1], aaddr1 + ko);
            LDSM4(bf[nxt][0], baddr0 + ko);
            LDSM4(bf[nxt][1], baddr1 + ko);
        }
        #pragma unroll
        for (int mt = 0; mt < 2; mt++) {
            #pragma unroll
            for (int p = 0; p < 2; p++) {
                mma_f16(acc[mt][2 * p],     af[cur][mt], &bf[cur][p][0]);
                mma_f16(acc[mt][2 * p + 1], af[cur][mt], &bf[cur][p][2]);
            }
        }
    }

    #pragma unroll
    for (int mt = 0; mt < 2; mt++) {
        int r = row0 + wm * 32 + mt * 16 + (lane >> 2);
        #pragma unroll
        for (int nt = 0; nt < 4; nt++) {
            int cl = wn * 32 + nt * 8 + ((lane & 3) << 1);
            float bx = sbias[cl], by = sbias[cl + 1];
            float2 v0 = { acc[mt][nt][0] + bx, acc[mt][nt][1] + by };
            float2 v1 = { acc[mt][nt][2] + bx, acc[mt][nt][3] + by };
            *(float2*)&out[(size_t)r * C + col0 + cl]       = v0;
            *(float2*)&out[(size_t)(r + 8) * C + col0 + cl] = v1;
        }
    }
}

// ---------------------------------------------------------------- launch
extern "C" void kernel_launch(void* const* d_in, const int* in_sizes, int n_in,
                              void* d_out, int out_size)
{
    const float* x  = nullptr;
    const float* Wm = nullptr;
    const int*   ei = nullptr;
    const float* b1 = nullptr;
    const float* b2 = nullptr;

    for (int i = 0; i < n_in; i++) {
        int s = in_sizes[i];
        if (s == N_NODES * C)        x  = (const float*)d_in[i];
        else if (s == C * C)         Wm = (const float*)d_in[i];
        else if (s == 2 * 131072)    ei = (const int*)d_in[i];
        else if (s == C) {
            if (!b1) b1 = (const float*)d_in[i];
            else     b2 = (const float*)d_in[i];
        }
    }
    if (!b2) b2 = b1;
    float* out = (float*)d_out;
    int E = 131072;

    static bool attr_done = false;
    if (!attr_done) {   // first call is the (uncaptured) correctness run
        cudaFuncSetAttribute(k_gemm_mma,
                             cudaFuncAttributeMaxDynamicSharedMemorySize,
                             SMEM_BYTES);
        attr_done = true;
    }

    k_set_edges<<<(E + 255) / 256, 256>>>(ei, E, Wm);
    k_prep<<<N_NODES / ROWS_PER_BLK, 256>>>(x);
    k_spmm<<<N_NODES / 8, 256>>>();
    k_gemm_mma<<<dim3(N_NODES / GT_M, C / GT_N), 512, SMEM_BYTES>>>(b1, b2, out);
}